// round 10
// baseline (speedup 1.0000x reference)
#include <cuda_runtime.h>
#include <cuda_fp16.h>
#include <cstdint>
#include <math.h>

static constexpr int Nd   = 8192;
static constexpr int Bd   = 256;
static constexpr int NNZc = 16 * Nd;
static constexpr int SLOTS = 64;          // padded CSR row capacity (max ~38 expected)

// ---------------- device scratch (no allocation) ----------------
__device__ __align__(1024) float  g_xt[Nd * Bd];        // x^T [N,B] fp32
__device__ __align__(1024) __half g_a0h[Bd * Nd];       // activations fp16 [B,N]
__device__ __align__(1024) __half g_h1h[Bd * Nd];
__device__ __align__(1024) __half g_h2h[Bd * Nd];
__device__ __align__(1024) __half g_w16[3u * Nd * Nd];  // fp16 weights (402 MB)
__device__ int   g_cnt[Nd];
__device__ __align__(1024) int2 g_cv[Nd * SLOTS];       // padded {col, val-bits}

// ---------------- helpers ----------------
__device__ __forceinline__ uint32_t smem_to_u32(const void* p) {
    uint32_t a;
    asm("{ .reg .u64 t; cvta.to.shared.u64 t, %1; cvt.u32.u64 %0, t; }" : "=r"(a) : "l"(p));
    return a;
}

__device__ __forceinline__ float selu_f(float x) {
    const float kS = 1.0507009873554805f;
    const float kA = 1.6732632423543772f;
    return x > 0.f ? kS * x : kS * kA * expm1f(x);
}

// tile with 128B rows (64 halves), SW128 swizzle. Used for both A and B (both fp16).
__device__ __forceinline__ uint32_t swz64h(uint32_t r, uint32_t c) {
    uint32_t byte = r * 128u + c * 2u;
    return byte ^ ((byte >> 3) & 0x70u);
}

#define CP_ASYNC16(dst, src) \
    asm volatile("cp.async.cg.shared.global [%0], [%1], 16;" :: "r"(dst), "l"(src) : "memory")
#define CP_COMMIT() asm volatile("cp.async.commit_group;" ::: "memory")
#define CP_WAIT2()  asm volatile("cp.async.wait_group 2;" ::: "memory")

#define LDMATRIX_X4(r0, r1, r2, r3, addr) \
    asm volatile("ldmatrix.sync.aligned.m8n8.x4.shared.b16 {%0,%1,%2,%3}, [%4];" \
        : "=r"(r0), "=r"(r1), "=r"(r2), "=r"(r3) : "r"(addr))

#define MMA16816(d, a, b0, b1) \
    asm volatile("mma.sync.aligned.m16n8k16.row.col.f32.f16.f16.f32 " \
        "{%0,%1,%2,%3}, {%4,%5,%6,%7}, {%8,%9}, {%0,%1,%2,%3};" \
        : "+f"((d)[0]), "+f"((d)[1]), "+f"((d)[2]), "+f"((d)[3]) \
        : "r"((a)[0]), "r"((a)[1]), "r"((a)[2]), "r"((a)[3]), "r"(b0), "r"(b1))

// ---------------- weight fp32 -> fp16 (runs on side stream) ----------------
__global__ void __launch_bounds__(256) convertw_kernel(const float* __restrict__ w,
                                                       __half* __restrict__ o) {
    int i = blockIdx.x * blockDim.x + threadIdx.x;   // 8 elements per thread
    const float4* s = (const float4*)w;
    float4 a = s[i * 2], b = s[i * 2 + 1];
    __half2 h0 = __floats2half2_rn(a.x, a.y);
    __half2 h1 = __floats2half2_rn(a.z, a.w);
    __half2 h2 = __floats2half2_rn(b.x, b.y);
    __half2 h3 = __floats2half2_rn(b.z, b.w);
    uint4 pk;
    pk.x = *(uint32_t*)&h0; pk.y = *(uint32_t*)&h1;
    pk.z = *(uint32_t*)&h2; pk.w = *(uint32_t*)&h3;
    ((uint4*)o)[i] = pk;
}

// ---------------- sparse pipeline ----------------
__global__ void __launch_bounds__(256, 2) fused_prep_kernel(const float* __restrict__ x) {
    if (blockIdx.x < 2048) {
        __shared__ float t[32][33];
        int nb = (blockIdx.x & 255) * 32, bb = (blockIdx.x >> 8) * 32;
        int tx = threadIdx.x & 31, ty = threadIdx.x >> 5;
#pragma unroll
        for (int i = 0; i < 32; i += 8)
            t[ty + i][tx] = x[(size_t)(bb + ty + i) * Nd + nb + tx];
        __syncthreads();
#pragma unroll
        for (int i = 0; i < 32; i += 8)
            g_xt[(size_t)(nb + ty + i) * Bd + bb + tx] = t[tx][ty + i];
    } else {
#pragma unroll
        for (int i = 0; i < Nd / 256; i++) g_cnt[threadIdx.x + i * 256] = 0;
    }
}

__global__ void build_kernel(const int* __restrict__ rows, const int* __restrict__ cols,
                             const float* __restrict__ vals) {
    for (int i = blockIdx.x * blockDim.x + threadIdx.x; i < NNZc; i += gridDim.x * blockDim.x) {
        int r = rows[i];
        int p = atomicAdd(&g_cnt[r], 1);
        g_cv[r * SLOTS + p] = make_int2(cols[i], __float_as_int(vals[i]));
    }
}

__global__ void spmv_kernel(const float* __restrict__ bc, const float* __restrict__ flag) {
    int row = blockIdx.x * 8 + (threadIdx.x >> 5);
    int lane = threadIdx.x & 31;
    int n = g_cnt[row];
    const int2* cv = g_cv + row * SLOTS;
    float a0 = 0.f, a1 = 0.f, a2 = 0.f, a3 = 0.f, a4 = 0.f, a5 = 0.f, a6 = 0.f, a7 = 0.f;
    const float* xb = g_xt + lane * 8;
    if (n > 0) {
        int2 c0 = cv[0];
        for (int j = 0; j < n; j++) {
            int2 c1 = (j + 1 < n) ? cv[j + 1] : c0;
            float v = __int_as_float(c0.y);
            const float4* p = (const float4*)(xb + (size_t)c0.x * Bd);
            float4 u = p[0], w = p[1];
            a0 += v * u.x; a1 += v * u.y; a2 += v * u.z; a3 += v * u.w;
            a4 += v * w.x; a5 += v * w.y; a6 += v * w.z; a7 += v * w.w;
            c0 = c1;
        }
    }
    float bcv = bc[row], fl = flag[row];
    float r[8] = {a0, a1, a2, a3, a4, a5, a6, a7};
#pragma unroll
    for (int i = 0; i < 8; i++)
        g_a0h[(size_t)(lane * 8 + i) * Nd + row] = __float2half_rn(bcv + r[i] * fl);
}

// ---------------- fp16 mma.sync GEMM (A and B both fp16, B via ldmatrix) ----------------
static constexpr int NSTAGE      = 4;
static constexpr int A_BYTES     = 16384;   // 128 x 64 halves
static constexpr int B_BYTES     = 16384;   // 128 x 64 halves
static constexpr int STAGE_BYTES = A_BYTES + B_BYTES;       // 32 KB
static constexpr int GEMM_SMEM   = NSTAGE * STAGE_BYTES;    // 128 KB
static constexpr int KTILES      = Nd / 64; // 128

__device__ __forceinline__ void issue_stage(uint32_t sbase, int buf,
                                            const __half* At, const __half* Wt,
                                            int k0, int tid) {
    uint32_t st = sbase + buf * STAGE_BYTES;
    // A: 128 rows x 8 chunks of 16B
#pragma unroll
    for (int i = 0; i < 4; i++) {
        int id = tid + i * 256;
        int r = id >> 3, ch = id & 7;
        const __half* src = At + (size_t)r * Nd + k0 + ch * 8;
        CP_ASYNC16(st + swz64h(r, ch * 8), src);
    }
    // B: 128 rows x 8 chunks of 16B
#pragma unroll
    for (int i = 0; i < 4; i++) {
        int id = tid + i * 256;
        int r = id >> 3, ch = id & 7;
        const __half* src = Wt + (size_t)r * Nd + k0 + ch * 8;
        CP_ASYNC16(st + A_BYTES + swz64h(r, ch * 8), src);
    }
}

struct Frags {
    uint32_t ar[4][4];
    uint32_t br[2][4];
};

__device__ __forceinline__ void load_frags(Frags& f, uint32_t sb,
                                           int stage, int ks, int wm, int wn, int lane) {
    uint32_t aB = sb + stage * STAGE_BYTES;
    uint32_t bB = aB + A_BYTES;
    uint32_t col = ks * 16 + (lane >> 4) * 8;
#pragma unroll
    for (int mf = 0; mf < 4; mf++) {
        uint32_t row = wm * 64 + mf * 16 + (lane & 15);
        LDMATRIX_X4(f.ar[mf][0], f.ar[mf][1], f.ar[mf][2], f.ar[mf][3],
                    aB + swz64h(row, col));
    }
#pragma unroll
    for (int p = 0; p < 2; p++) {
        uint32_t row = wn * 32 + p * 16 + (lane & 15);
        LDMATRIX_X4(f.br[p][0], f.br[p][1], f.br[p][2], f.br[p][3],
                    bB + swz64h(row, col));
    }
}

__global__ void __launch_bounds__(256, 1)
gemm_f16_kernel(const __half* __restrict__ Ag, const __half* __restrict__ Wg,
                const float* __restrict__ bias,
                const float* __restrict__ bc, const float* __restrict__ flag,
                void* __restrict__ outv, int mode)   // 0=selu->half, 1=addcmul->float
{
    extern __shared__ char smem[];
    uint32_t sb = smem_to_u32(smem);
    int tid = threadIdx.x, lane = tid & 31, w = tid >> 5;
    int wm = w & 1, wn = w >> 1;          // warp tile 64 x 32
    int mtile = blockIdx.x & 1, ntile = blockIdx.x >> 1;   // CTA tile 128 x 128

    const __half* At = Ag + (size_t)(mtile * 128) * Nd;
    const __half* Wt = Wg + (size_t)(ntile * 128) * Nd;

    float acc[4][4][4];
#pragma unroll
    for (int a = 0; a < 4; a++)
#pragma unroll
        for (int b = 0; b < 4; b++)
#pragma unroll
            for (int c = 0; c < 4; c++) acc[a][b][c] = 0.f;

#pragma unroll
    for (int s = 0; s < NSTAGE - 1; s++) {          // stages 0,1,2
        issue_stage(sb, s, At, Wt, s * 64, tid);
        CP_COMMIT();
    }

    Frags f0, f1;
#pragma unroll 1
    for (int t = 0; t < KTILES; t++) {
        // committed groups: 3 + t; wait 2 -> groups 0..t complete -> stage t ready
        CP_WAIT2();
        __syncthreads();     // stage t visible; stage t-1 reads all complete
        if (t + 3 < KTILES)
            issue_stage(sb, (t + 3) % NSTAGE, At, Wt, (t + 3) * 64, tid);
        CP_COMMIT();         // unconditional: exact group accounting

        int st = t % NSTAGE;
        load_frags(f0, sb, st, 0, wm, wn, lane);
#pragma unroll
        for (int ks = 0; ks < 4; ks++) {
            Frags& cur = (ks & 1) ? f1 : f0;
            Frags& nxt = (ks & 1) ? f0 : f1;
            if (ks < 3) load_frags(nxt, sb, st, ks + 1, wm, wn, lane);
#pragma unroll
            for (int mf = 0; mf < 4; mf++)
#pragma unroll
                for (int nf = 0; nf < 4; nf++) {
                    uint32_t b0 = cur.br[nf >> 1][nf & 1];
                    uint32_t b1 = cur.br[nf >> 1][2 + (nf & 1)];
                    MMA16816(acc[mf][nf], cur.ar[mf], b0, b1);
                }
        }
    }

#pragma unroll
    for (int mf = 0; mf < 4; mf++) {
#pragma unroll
        for (int nf = 0; nf < 4; nf++) {
            int r0 = mtile * 128 + wm * 64 + mf * 16 + (lane >> 2);
            int c0 = ntile * 128 + wn * 32 + nf * 8 + (lane & 3) * 2;
            float b0 = __ldg(&bias[c0]), b1 = __ldg(&bias[c0 + 1]);
            float v00 = acc[mf][nf][0] + b0, v01 = acc[mf][nf][1] + b1;
            float v10 = acc[mf][nf][2] + b0, v11 = acc[mf][nf][3] + b1;
            if (mode == 0) {
                __half2* o0 = (__half2*)((__half*)outv + (size_t)r0 * Nd + c0);
                __half2* o1 = (__half2*)((__half*)outv + (size_t)(r0 + 8) * Nd + c0);
                *o0 = __floats2half2_rn(selu_f(v00), selu_f(v01));
                *o1 = __floats2half2_rn(selu_f(v10), selu_f(v11));
            } else {
                float bc0 = __ldg(&bc[c0]), bc1 = __ldg(&bc[c0 + 1]);
                float fl0 = __ldg(&flag[c0]), fl1 = __ldg(&flag[c0 + 1]);
                float* o0 = (float*)outv + (size_t)r0 * Nd + c0;
                float* o1 = (float*)outv + (size_t)(r0 + 8) * Nd + c0;
                o0[0] = bc0 + v00 * fl0; o0[1] = bc1 + v01 * fl1;
                o1[0] = bc0 + v10 * fl0; o1[1] = bc1 + v11 * fl1;
            }
        }
    }
}

// ---------------- host ----------------
extern "C" void kernel_launch(void* const* d_in, const int* in_sizes, int n_in,
                              void* d_out, int out_size) {
    const float* x    = (const float*)d_in[0];
    const float* vals = (const float*)d_in[1];
    const float* bc   = (const float*)d_in[2];
    const float* flag = (const float*)d_in[3];
    const float* W1   = (const float*)d_in[4];
    const float* b1   = (const float*)d_in[5];
    const float* W2   = (const float*)d_in[6];
    const float* b2   = (const float*)d_in[7];
    const float* W3   = (const float*)d_in[8];
    const float* b3   = (const float*)d_in[9];
    const int*   rows = (const int*)d_in[10];
    const int*   cols = (const int*)d_in[11];

    void *pa0, *ph1, *ph2, *pw;
    cudaGetSymbolAddress(&pa0, g_a0h);
    cudaGetSymbolAddress(&ph1, g_h1h);
    cudaGetSymbolAddress(&ph2, g_h2h);
    cudaGetSymbolAddress(&pw,  g_w16);
    __half* w16a = (__half*)pw;
    __half* w16b = w16a + (size_t)Nd * Nd;
    __half* w16c = w16b + (size_t)Nd * Nd;

    cudaFuncSetAttribute(gemm_f16_kernel, cudaFuncAttributeMaxDynamicSharedMemorySize, GEMM_SMEM);

    // fork a side stream for weight conversion; join before each GEMM.
    cudaStream_t s2;
    cudaStreamCreateWithFlags(&s2, cudaStreamNonBlocking);
    cudaEvent_t ev0, evc1, evc2, evc3;
    cudaEventCreateWithFlags(&ev0,  cudaEventDisableTiming);
    cudaEventCreateWithFlags(&evc1, cudaEventDisableTiming);
    cudaEventCreateWithFlags(&evc2, cudaEventDisableTiming);
    cudaEventCreateWithFlags(&evc3, cudaEventDisableTiming);

    const int cwBlocks = (Nd * Nd / 8) / 256;   // 32768

    cudaEventRecord(ev0, 0);
    cudaStreamWaitEvent(s2, ev0, 0);
    convertw_kernel<<<cwBlocks, 256, 0, s2>>>(W1, w16a);
    cudaEventRecord(evc1, s2);
    convertw_kernel<<<cwBlocks, 256, 0, s2>>>(W2, w16b);
    cudaEventRecord(evc2, s2);
    convertw_kernel<<<cwBlocks, 256, 0, s2>>>(W3, w16c);
    cudaEventRecord(evc3, s2);

    // main stream: sparse front overlaps convert1
    fused_prep_kernel<<<2049, 256>>>(x);
    build_kernel<<<256, 256>>>(rows, cols, vals);
    spmv_kernel<<<Nd / 8, 256>>>(bc, flag);

    cudaStreamWaitEvent(0, evc1, 0);
    gemm_f16_kernel<<<128, 256, GEMM_SMEM>>>((__half*)pa0, w16a, b1, bc, flag, ph1, 0);
    cudaStreamWaitEvent(0, evc2, 0);
    gemm_f16_kernel<<<128, 256, GEMM_SMEM>>>((__half*)ph1, w16b, b2, bc, flag, ph2, 0);
    cudaStreamWaitEvent(0, evc3, 0);
    gemm_f16_kernel<<<128, 256, GEMM_SMEM>>>((__half*)ph2, w16c, b3, bc, flag, d_out, 1);

    cudaEventDestroy(ev0);
    cudaEventDestroy(evc1);
    cudaEventDestroy(evc2);
    cudaEventDestroy(evc3);
    cudaStreamDestroy(s2);
}

// round 11
// speedup vs baseline: 1.3689x; 1.3689x over previous
#include <cuda_runtime.h>
#include <cuda_fp16.h>
#include <cstdint>
#include <math.h>

static constexpr int Nd   = 8192;
static constexpr int Bd   = 256;
static constexpr int NNZc = 16 * Nd;
static constexpr int SLOTS = 64;          // padded CSR row capacity (max ~38 expected)

// ---------------- device scratch (no allocation) ----------------
__device__ __align__(1024) __half g_xth[Nd * Bd];       // x^T [N,B] fp16
__device__ __align__(1024) __half g_a0h[Bd * Nd];       // activations fp16 [B,N]
__device__ __align__(1024) __half g_h1h[Bd * Nd];
__device__ __align__(1024) __half g_h2h[Bd * Nd];
__device__ int   g_cnt[Nd];
__device__ __align__(1024) int2 g_cv[Nd * SLOTS];       // padded {col, val-bits}

// ---------------- helpers ----------------
__device__ __forceinline__ uint32_t smem_to_u32(const void* p) {
    uint32_t a;
    asm("{ .reg .u64 t; cvta.to.shared.u64 t, %1; cvt.u32.u64 %0, t; }" : "=r"(a) : "l"(p));
    return a;
}

__device__ __forceinline__ float selu_f(float x) {
    const float kS = 1.0507009873554805f;
    const float kA = 1.6732632423543772f;
    return x > 0.f ? kS * x : kS * kA * expm1f(x);
}

// A tile: 128 rows x 64 halves = 128B rows, SW128
__device__ __forceinline__ uint32_t swzA64(uint32_t r, uint32_t c) {
    uint32_t byte = r * 128u + c * 2u;
    return byte ^ ((byte >> 3) & 0x70u);
}
// B tile: 128 rows x 64 fp32 = 256B rows, SW128
__device__ __forceinline__ uint32_t swzB64(uint32_t r, uint32_t cw) {
    uint32_t byte = r * 256u + cw * 4u;
    return byte ^ ((byte >> 3) & 0x70u);
}

#define CP_ASYNC16(dst, src) \
    asm volatile("cp.async.cg.shared.global [%0], [%1], 16;" :: "r"(dst), "l"(src) : "memory")
#define CP_COMMIT() asm volatile("cp.async.commit_group;" ::: "memory")
#define CP_WAIT1()  asm volatile("cp.async.wait_group 1;" ::: "memory")

#define LDMATRIX_X4(r0, r1, r2, r3, addr) \
    asm volatile("ldmatrix.sync.aligned.m8n8.x4.shared.b16 {%0,%1,%2,%3}, [%4];" \
        : "=r"(r0), "=r"(r1), "=r"(r2), "=r"(r3) : "r"(addr))

#define MMA16816(d, a, b0, b1) \
    asm volatile("mma.sync.aligned.m16n8k16.row.col.f32.f16.f16.f32 " \
        "{%0,%1,%2,%3}, {%4,%5,%6,%7}, {%8,%9}, {%0,%1,%2,%3};" \
        : "+f"((d)[0]), "+f"((d)[1]), "+f"((d)[2]), "+f"((d)[3]) \
        : "r"((a)[0]), "r"((a)[1]), "r"((a)[2]), "r"((a)[3]), "r"(b0), "r"(b1))

// ---------------- sparse pipeline (3 launches) ----------------
__global__ void __launch_bounds__(256, 2) fused_prep_kernel(const float* __restrict__ x) {
    if (blockIdx.x < 2048) {
        __shared__ float t[32][33];
        int nb = (blockIdx.x & 255) * 32, bb = (blockIdx.x >> 8) * 32;
        int tx = threadIdx.x & 31, ty = threadIdx.x >> 5;
#pragma unroll
        for (int i = 0; i < 32; i += 8)
            t[ty + i][tx] = x[(size_t)(bb + ty + i) * Nd + nb + tx];
        __syncthreads();
#pragma unroll
        for (int i = 0; i < 32; i += 8)
            g_xth[(size_t)(nb + ty + i) * Bd + bb + tx] = __float2half_rn(t[tx][ty + i]);
    } else {
#pragma unroll
        for (int i = 0; i < Nd / 256; i++) g_cnt[threadIdx.x + i * 256] = 0;
    }
}

__global__ void build_kernel(const int* __restrict__ rows, const int* __restrict__ cols,
                             const float* __restrict__ vals) {
    for (int i = blockIdx.x * blockDim.x + threadIdx.x; i < NNZc; i += gridDim.x * blockDim.x) {
        int r = rows[i];
        int p = atomicAdd(&g_cnt[r], 1);
        g_cv[r * SLOTS + p] = make_int2(cols[i], __float_as_int(vals[i]));
    }
}

__global__ void spmv_kernel(const float* __restrict__ bc, const float* __restrict__ flag) {
    int row = blockIdx.x * 8 + (threadIdx.x >> 5);
    int lane = threadIdx.x & 31;
    int n = g_cnt[row];
    const int2* cv = g_cv + row * SLOTS;
    const __half* xbh = g_xth + lane * 8;
    float a0 = 0.f, a1 = 0.f, a2 = 0.f, a3 = 0.f, a4 = 0.f, a5 = 0.f, a6 = 0.f, a7 = 0.f;
    if (n > 0) {
        int2 c = cv[0];
        uint4 raw = *(const uint4*)(xbh + (size_t)c.x * Bd);
        for (int j = 0; j < n; j++) {
            float v = __int_as_float(c.y);
            int2 cn = c; uint4 rn = raw;
            if (j + 1 < n) {                         // prefetch next (cv, x-row)
                cn = cv[j + 1];
                rn = *(const uint4*)(xbh + (size_t)cn.x * Bd);
            }
            __half2* h = (__half2*)&raw;
            float2 p0 = __half22float2(h[0]);
            float2 p1 = __half22float2(h[1]);
            float2 p2 = __half22float2(h[2]);
            float2 p3 = __half22float2(h[3]);
            a0 += v * p0.x; a1 += v * p0.y; a2 += v * p1.x; a3 += v * p1.y;
            a4 += v * p2.x; a5 += v * p2.y; a6 += v * p3.x; a7 += v * p3.y;
            c = cn; raw = rn;
        }
    }
    float bcv = bc[row], fl = flag[row];
    float r[8] = {a0, a1, a2, a3, a4, a5, a6, a7};
#pragma unroll
    for (int i = 0; i < 8; i++)
        g_a0h[(size_t)(lane * 8 + i) * Nd + row] = __float2half_rn(bcv + r[i] * fl);
}

// ---------------- fp16 mma.sync GEMM, fp32 W converted in-register ----------------
static constexpr int NSTAGE      = 4;
static constexpr int A_BYTES     = 16384;   // 128x64 halves
static constexpr int B_BYTES     = 32768;   // 128x64 fp32
static constexpr int STAGE_BYTES = A_BYTES + B_BYTES;           // 48 KB
static constexpr int GEMM_SMEM   = NSTAGE * STAGE_BYTES;        // 192 KB
static constexpr int KTILES      = Nd / 64; // 128

__device__ __forceinline__ void issue_stage(uint32_t sbase, int buf,
                                            const __half* At, const float* Wt,
                                            int k0, int tid) {
    uint32_t st = sbase + buf * STAGE_BYTES;
    // A: 1024 x 16B chunks (128B/row = 8 chunks)
#pragma unroll
    for (int i = 0; i < 4; i++) {
        int id = tid + i * 256;
        int r = id >> 3, ch = id & 7;
        const __half* src = At + (size_t)r * Nd + k0 + ch * 8;
        CP_ASYNC16(st + swzA64(r, ch * 8), src);
    }
    // B: 2048 x 16B chunks (256B/row = 16 chunks)
#pragma unroll
    for (int i = 0; i < 8; i++) {
        int id = tid + i * 256;
        int r = id >> 4, ch = id & 15;
        const float* src = Wt + (size_t)r * Nd + k0 + ch * 4;
        CP_ASYNC16(st + A_BYTES + swzB64(r, ch * 4), src);
    }
}

struct Frags {
    uint32_t ar[4][4];
    uint32_t b0r[4], b1r[4];
};

__device__ __forceinline__ void load_frags(Frags& f, const char* smem,
                                           int stage, int ks, int wm, int wn, int lane) {
    uint32_t aOff = stage * STAGE_BYTES;
    uint32_t bOff = aOff + A_BYTES;
    uint32_t sb0 = smem_to_u32(smem);
    uint32_t acol = ks * 16 + (lane >> 4) * 8;
#pragma unroll
    for (int mf = 0; mf < 4; mf++) {
        uint32_t row = wm * 64 + mf * 16 + (lane & 15);
        LDMATRIX_X4(f.ar[mf][0], f.ar[mf][1], f.ar[mf][2], f.ar[mf][3],
                    sb0 + aOff + swzA64(row, acol));
    }
    uint32_t nrow = wn * 32 + (lane >> 2);
    uint32_t clo = ks * 16 + (lane & 3) * 2;
#pragma unroll
    for (int nf = 0; nf < 4; nf++) {
        uint32_t r = nrow + nf * 8;
        float2 lo = *(const float2*)(smem + bOff + swzB64(r, clo));
        float2 hi = *(const float2*)(smem + bOff + swzB64(r, clo + 8));
        __half2 h0 = __floats2half2_rn(lo.x, lo.y);
        __half2 h1 = __floats2half2_rn(hi.x, hi.y);
        f.b0r[nf] = *(uint32_t*)&h0;
        f.b1r[nf] = *(uint32_t*)&h1;
    }
}

__global__ void __launch_bounds__(256, 1)
gemm_f16_kernel(const __half* __restrict__ Ag, const float* __restrict__ Wg,
                const float* __restrict__ bias,
                const float* __restrict__ bc, const float* __restrict__ flag,
                void* __restrict__ outv, int mode)   // 0=selu->half, 1=addcmul->float
{
    extern __shared__ char smem[];
    uint32_t sb = smem_to_u32(smem);
    int tid = threadIdx.x, lane = tid & 31, w = tid >> 5;
    int wm = w & 1, wn = w >> 1;
    int mtile = blockIdx.x & 1, ntile = blockIdx.x >> 1;

    const __half* At = Ag + (size_t)(mtile * 128) * Nd;
    const float*  Wt = Wg + (size_t)(ntile * 128) * Nd;

    float acc[4][4][4];
#pragma unroll
    for (int a = 0; a < 4; a++)
#pragma unroll
        for (int b = 0; b < 4; b++)
#pragma unroll
            for (int c = 0; c < 4; c++) acc[a][b][c] = 0.f;

#pragma unroll
    for (int s = 0; s < NSTAGE - 1; s++) {          // stages 0,1,2
        issue_stage(sb, s, At, Wt, s * 64, tid);
        CP_COMMIT();
    }
    // stages 0 AND 1 complete (committed=3, wait_group 1), then preload f0(0,0)
    CP_WAIT1();
    __syncthreads();

    Frags f0, f1;
    load_frags(f0, smem, 0, 0, wm, wn, lane);

#pragma unroll 1
    for (int t = 0; t < KTILES; t++) {
        // committed = 3 + t; wait 1 -> groups 0..t+1 complete -> stages t, t+1 ready
        CP_WAIT1();
        __syncthreads();     // cross-thread visibility of stages t, t+1;
                             // all reads of stage t-1 (overwrite target) are done
        if (t + 3 < KTILES)
            issue_stage(sb, (t + 3) % NSTAGE, At, Wt, (t + 3) * 64, tid);
        CP_COMMIT();         // unconditional: exact group accounting

        int st = t % NSTAGE;
        int sn = (t + 1) % NSTAGE;

        // ks=0: load (t,1) over MMA(t,0)
        load_frags(f1, smem, st, 1, wm, wn, lane);
#pragma unroll
        for (int mf = 0; mf < 4; mf++)
#pragma unroll
            for (int nf = 0; nf < 4; nf++)
                MMA16816(acc[mf][nf], f0.ar[mf], f0.b0r[nf], f0.b1r[nf]);
        // ks=1: load (t,2) over MMA(t,1)
        load_frags(f0, smem, st, 2, wm, wn, lane);
#pragma unroll
        for (int mf = 0; mf < 4; mf++)
#pragma unroll
            for (int nf = 0; nf < 4; nf++)
                MMA16816(acc[mf][nf], f1.ar[mf], f1.b0r[nf], f1.b1r[nf]);
        // ks=2: load (t,3) over MMA(t,2)
        load_frags(f1, smem, st, 3, wm, wn, lane);
#pragma unroll
        for (int mf = 0; mf < 4; mf++)
#pragma unroll
            for (int nf = 0; nf < 4; nf++)
                MMA16816(acc[mf][nf], f0.ar[mf], f0.b0r[nf], f0.b1r[nf]);
        // ks=3: load (t+1,0) (stage t+1 already readable) over MMA(t,3)
        if (t + 1 < KTILES)
            load_frags(f0, smem, sn, 0, wm, wn, lane);
#pragma unroll
        for (int mf = 0; mf < 4; mf++)
#pragma unroll
            for (int nf = 0; nf < 4; nf++)
                MMA16816(acc[mf][nf], f1.ar[mf], f1.b0r[nf], f1.b1r[nf]);
    }

#pragma unroll
    for (int mf = 0; mf < 4; mf++) {
#pragma unroll
        for (int nf = 0; nf < 4; nf++) {
            int r0 = mtile * 128 + wm * 64 + mf * 16 + (lane >> 2);
            int c0 = ntile * 128 + wn * 32 + nf * 8 + (lane & 3) * 2;
            float b0 = __ldg(&bias[c0]), b1 = __ldg(&bias[c0 + 1]);
            float v00 = acc[mf][nf][0] + b0, v01 = acc[mf][nf][1] + b1;
            float v10 = acc[mf][nf][2] + b0, v11 = acc[mf][nf][3] + b1;
            if (mode == 0) {
                __half2* o0 = (__half2*)((__half*)outv + (size_t)r0 * Nd + c0);
                __half2* o1 = (__half2*)((__half*)outv + (size_t)(r0 + 8) * Nd + c0);
                *o0 = __floats2half2_rn(selu_f(v00), selu_f(v01));
                *o1 = __floats2half2_rn(selu_f(v10), selu_f(v11));
            } else {
                float bc0 = __ldg(&bc[c0]), bc1 = __ldg(&bc[c0 + 1]);
                float fl0 = __ldg(&flag[c0]), fl1 = __ldg(&flag[c0 + 1]);
                float* o0 = (float*)outv + (size_t)r0 * Nd + c0;
                float* o1 = (float*)outv + (size_t)(r0 + 8) * Nd + c0;
                o0[0] = bc0 + v00 * fl0; o0[1] = bc1 + v01 * fl1;
                o1[0] = bc0 + v10 * fl0; o1[1] = bc1 + v11 * fl1;
            }
        }
    }
}

// ---------------- host ----------------
extern "C" void kernel_launch(void* const* d_in, const int* in_sizes, int n_in,
                              void* d_out, int out_size) {
    const float* x    = (const float*)d_in[0];
    const float* vals = (const float*)d_in[1];
    const float* bc   = (const float*)d_in[2];
    const float* flag = (const float*)d_in[3];
    const float* W1   = (const float*)d_in[4];
    const float* b1   = (const float*)d_in[5];
    const float* W2   = (const float*)d_in[6];
    const float* b2   = (const float*)d_in[7];
    const float* W3   = (const float*)d_in[8];
    const float* b3   = (const float*)d_in[9];
    const int*   rows = (const int*)d_in[10];
    const int*   cols = (const int*)d_in[11];

    void *pa0, *ph1, *ph2;
    cudaGetSymbolAddress(&pa0, g_a0h);
    cudaGetSymbolAddress(&ph1, g_h1h);
    cudaGetSymbolAddress(&ph2, g_h2h);

    cudaFuncSetAttribute(gemm_f16_kernel, cudaFuncAttributeMaxDynamicSharedMemorySize, GEMM_SMEM);

    fused_prep_kernel<<<2049, 256>>>(x);                                  // 0
    build_kernel<<<256, 256>>>(rows, cols, vals);                         // 1
    spmv_kernel<<<Nd / 8, 256>>>(bc, flag);                               // 2
    gemm_f16_kernel<<<128, 256, GEMM_SMEM>>>((__half*)pa0, W1, b1, bc, flag, ph1, 0);   // 3 <- ncu
    gemm_f16_kernel<<<128, 256, GEMM_SMEM>>>((__half*)ph1, W2, b2, bc, flag, ph2, 0);   // 4
    gemm_f16_kernel<<<128, 256, GEMM_SMEM>>>((__half*)ph2, W3, b3, bc, flag, d_out, 1); // 5
}

// round 12
// speedup vs baseline: 1.3875x; 1.0136x over previous
#include <cuda_runtime.h>
#include <cuda_fp16.h>
#include <cstdint>
#include <math.h>

static constexpr int Nd   = 8192;
static constexpr int Bd   = 256;
static constexpr int NNZc = 16 * Nd;
static constexpr int SLOTS = 64;          // padded CSR row capacity (max ~38 expected)

// ---------------- device scratch (no allocation) ----------------
__device__ __align__(1024) __half g_xth[Nd * Bd];       // x^T [N,B] fp16
__device__ __align__(1024) __half g_a0h[Bd * Nd];       // activations fp16 [B,N]
__device__ __align__(1024) __half g_h1h[Bd * Nd];
__device__ __align__(1024) __half g_h2h[Bd * Nd];
__device__ int   g_cnt[Nd];
__device__ __align__(1024) int2 g_cv[Nd * SLOTS];       // padded {col, val-bits}

// ---------------- helpers ----------------
__device__ __forceinline__ uint32_t smem_to_u32(const void* p) {
    uint32_t a;
    asm("{ .reg .u64 t; cvta.to.shared.u64 t, %1; cvt.u32.u64 %0, t; }" : "=r"(a) : "l"(p));
    return a;
}

__device__ __forceinline__ float selu_f(float x) {
    const float kS = 1.0507009873554805f;
    const float kA = 1.6732632423543772f;
    return x > 0.f ? kS * x : kS * kA * expm1f(x);
}

// A tile: 128 rows x 64 halves = 128B rows, SW128 (canonical, conflict-free for ldsm)
__device__ __forceinline__ uint32_t swzA64(uint32_t r, uint32_t c) {
    uint32_t byte = r * 128u + c * 2u;
    return byte ^ ((byte >> 3) & 0x70u);
}
// B tile: 128 rows x 64 fp32 = 256B rows.
// XOR row bits (r&7) into byte-bits [7:5] (32B granule): involution, 16B-chunk-preserving,
// and the 8-row x 4-lane lds.64 fragment pattern becomes bank-conflict-free per wavefront.
__device__ __forceinline__ uint32_t swzB64(uint32_t r, uint32_t cw) {
    uint32_t byte = r * 256u + cw * 4u;
    return byte ^ ((byte >> 3) & 0xE0u);
}

#define CP_ASYNC16(dst, src) \
    asm volatile("cp.async.cg.shared.global [%0], [%1], 16;" :: "r"(dst), "l"(src) : "memory")
#define CP_COMMIT() asm volatile("cp.async.commit_group;" ::: "memory")
#define CP_WAIT1()  asm volatile("cp.async.wait_group 1;" ::: "memory")

#define LDMATRIX_X4(r0, r1, r2, r3, addr) \
    asm volatile("ldmatrix.sync.aligned.m8n8.x4.shared.b16 {%0,%1,%2,%3}, [%4];" \
        : "=r"(r0), "=r"(r1), "=r"(r2), "=r"(r3) : "r"(addr))

#define MMA16816(d, a, b0, b1) \
    asm volatile("mma.sync.aligned.m16n8k16.row.col.f32.f16.f16.f32 " \
        "{%0,%1,%2,%3}, {%4,%5,%6,%7}, {%8,%9}, {%0,%1,%2,%3};" \
        : "+f"((d)[0]), "+f"((d)[1]), "+f"((d)[2]), "+f"((d)[3]) \
        : "r"((a)[0]), "r"((a)[1]), "r"((a)[2]), "r"((a)[3]), "r"(b0), "r"(b1))

// ---------------- sparse pipeline (3 launches) ----------------
__global__ void __launch_bounds__(256, 2) fused_prep_kernel(const float* __restrict__ x) {
    if (blockIdx.x < 2048) {
        __shared__ float t[32][33];
        int nb = (blockIdx.x & 255) * 32, bb = (blockIdx.x >> 8) * 32;
        int tx = threadIdx.x & 31, ty = threadIdx.x >> 5;
#pragma unroll
        for (int i = 0; i < 32; i += 8)
            t[ty + i][tx] = x[(size_t)(bb + ty + i) * Nd + nb + tx];
        __syncthreads();
#pragma unroll
        for (int i = 0; i < 32; i += 8)
            g_xth[(size_t)(nb + ty + i) * Bd + bb + tx] = __float2half_rn(t[tx][ty + i]);
    } else {
#pragma unroll
        for (int i = 0; i < Nd / 256; i++) g_cnt[threadIdx.x + i * 256] = 0;
    }
}

__global__ void build_kernel(const int* __restrict__ rows, const int* __restrict__ cols,
                             const float* __restrict__ vals) {
    for (int i = blockIdx.x * blockDim.x + threadIdx.x; i < NNZc; i += gridDim.x * blockDim.x) {
        int r = rows[i];
        int p = atomicAdd(&g_cnt[r], 1);
        g_cv[r * SLOTS + p] = make_int2(cols[i], __float_as_int(vals[i]));
    }
}

__global__ void spmv_kernel(const float* __restrict__ bc, const float* __restrict__ flag) {
    int row = blockIdx.x * 8 + (threadIdx.x >> 5);
    int lane = threadIdx.x & 31;
    int n = g_cnt[row];
    const int2* cv = g_cv + row * SLOTS;
    const __half* xbh = g_xth + lane * 8;
    float a0 = 0.f, a1 = 0.f, a2 = 0.f, a3 = 0.f, a4 = 0.f, a5 = 0.f, a6 = 0.f, a7 = 0.f;
    if (n > 0) {
        int2 c = cv[0];
        uint4 raw = *(const uint4*)(xbh + (size_t)c.x * Bd);
        for (int j = 0; j < n; j++) {
            float v = __int_as_float(c.y);
            int2 cn = c; uint4 rn = raw;
            if (j + 1 < n) {                         // prefetch next (cv, x-row)
                cn = cv[j + 1];
                rn = *(const uint4*)(xbh + (size_t)cn.x * Bd);
            }
            __half2* h = (__half2*)&raw;
            float2 p0 = __half22float2(h[0]);
            float2 p1 = __half22float2(h[1]);
            float2 p2 = __half22float2(h[2]);
            float2 p3 = __half22float2(h[3]);
            a0 += v * p0.x; a1 += v * p0.y; a2 += v * p1.x; a3 += v * p1.y;
            a4 += v * p2.x; a5 += v * p2.y; a6 += v * p3.x; a7 += v * p3.y;
            c = cn; raw = rn;
        }
    }
    float bcv = bc[row], fl = flag[row];
    float r[8] = {a0, a1, a2, a3, a4, a5, a6, a7};
#pragma unroll
    for (int i = 0; i < 8; i++)
        g_a0h[(size_t)(lane * 8 + i) * Nd + row] = __float2half_rn(bcv + r[i] * fl);
}

// ---------------- fp16 mma.sync GEMM, fp32 W converted in-register ----------------
static constexpr int NSTAGE      = 4;
static constexpr int A_BYTES     = 16384;   // 128x64 halves
static constexpr int B_BYTES     = 32768;   // 128x64 fp32
static constexpr int STAGE_BYTES = A_BYTES + B_BYTES;           // 48 KB
static constexpr int GEMM_SMEM   = NSTAGE * STAGE_BYTES;        // 192 KB
static constexpr int KTILES      = Nd / 64; // 128

__device__ __forceinline__ void issue_stage(uint32_t sbase, int buf,
                                            const __half* At, const float* Wt,
                                            int k0, int tid) {
    uint32_t st = sbase + buf * STAGE_BYTES;
    // A: 1024 x 16B chunks (128B/row = 8 chunks)
#pragma unroll
    for (int i = 0; i < 4; i++) {
        int id = tid + i * 256;
        int r = id >> 3, ch = id & 7;
        const __half* src = At + (size_t)r * Nd + k0 + ch * 8;
        CP_ASYNC16(st + swzA64(r, ch * 8), src);
    }
    // B: 2048 x 16B chunks (256B/row = 16 chunks)
#pragma unroll
    for (int i = 0; i < 8; i++) {
        int id = tid + i * 256;
        int r = id >> 4, ch = id & 15;
        const float* src = Wt + (size_t)r * Nd + k0 + ch * 4;
        CP_ASYNC16(st + A_BYTES + swzB64(r, ch * 4), src);
    }
}

struct Frags {
    uint32_t ar[4][4];
    uint32_t b0r[4], b1r[4];
};

__device__ __forceinline__ void load_frags(Frags& f, const char* smem,
                                           int stage, int ks, int wm, int wn, int lane) {
    uint32_t aOff = stage * STAGE_BYTES;
    uint32_t bOff = aOff + A_BYTES;
    uint32_t sb0 = smem_to_u32(smem);
    uint32_t acol = ks * 16 + (lane >> 4) * 8;
#pragma unroll
    for (int mf = 0; mf < 4; mf++) {
        uint32_t row = wm * 64 + mf * 16 + (lane & 15);
        LDMATRIX_X4(f.ar[mf][0], f.ar[mf][1], f.ar[mf][2], f.ar[mf][3],
                    sb0 + aOff + swzA64(row, acol));
    }
    uint32_t nrow = wn * 32 + (lane >> 2);
    uint32_t clo = ks * 16 + (lane & 3) * 2;
#pragma unroll
    for (int nf = 0; nf < 4; nf++) {
        uint32_t r = nrow + nf * 8;
        float2 lo = *(const float2*)(smem + bOff + swzB64(r, clo));
        float2 hi = *(const float2*)(smem + bOff + swzB64(r, clo + 8));
        __half2 h0 = __floats2half2_rn(lo.x, lo.y);
        __half2 h1 = __floats2half2_rn(hi.x, hi.y);
        f.b0r[nf] = *(uint32_t*)&h0;
        f.b1r[nf] = *(uint32_t*)&h1;
    }
}

__global__ void __launch_bounds__(256, 1)
gemm_f16_kernel(const __half* __restrict__ Ag, const float* __restrict__ Wg,
                const float* __restrict__ bias,
                const float* __restrict__ bc, const float* __restrict__ flag,
                void* __restrict__ outv, int mode)   // 0=selu->half, 1=addcmul->float
{
    extern __shared__ char smem[];
    uint32_t sb = smem_to_u32(smem);
    int tid = threadIdx.x, lane = tid & 31, w = tid >> 5;
    int wm = w & 1, wn = w >> 1;
    int mtile = blockIdx.x & 1, ntile = blockIdx.x >> 1;

    const __half* At = Ag + (size_t)(mtile * 128) * Nd;
    const float*  Wt = Wg + (size_t)(ntile * 128) * Nd;

    float acc[4][4][4];
#pragma unroll
    for (int a = 0; a < 4; a++)
#pragma unroll
        for (int b = 0; b < 4; b++)
#pragma unroll
            for (int c = 0; c < 4; c++) acc[a][b][c] = 0.f;

#pragma unroll
    for (int s = 0; s < NSTAGE - 1; s++) {          // stages 0,1,2
        issue_stage(sb, s, At, Wt, s * 64, tid);
        CP_COMMIT();
    }
    // stages 0 AND 1 complete (committed=3, wait_group 1), then preload f0(0,0)
    CP_WAIT1();
    __syncthreads();

    Frags f0, f1;
    load_frags(f0, smem, 0, 0, wm, wn, lane);

#pragma unroll 1
    for (int t = 0; t < KTILES; t++) {
        // committed = 3 + t; wait 1 -> groups 0..t+1 complete -> stages t, t+1 ready
        CP_WAIT1();
        __syncthreads();     // cross-thread visibility of stages t, t+1;
                             // all reads of stage t-1 (overwrite target) are done
        if (t + 3 < KTILES)
            issue_stage(sb, (t + 3) % NSTAGE, At, Wt, (t + 3) * 64, tid);
        CP_COMMIT();         // unconditional: exact group accounting

        int st = t % NSTAGE;
        int sn = (t + 1) % NSTAGE;

        // ks=0: load (t,1) over MMA(t,0)
        load_frags(f1, smem, st, 1, wm, wn, lane);
#pragma unroll
        for (int mf = 0; mf < 4; mf++)
#pragma unroll
            for (int nf = 0; nf < 4; nf++)
                MMA16816(acc[mf][nf], f0.ar[mf], f0.b0r[nf], f0.b1r[nf]);
        // ks=1: load (t,2) over MMA(t,1)
        load_frags(f0, smem, st, 2, wm, wn, lane);
#pragma unroll
        for (int mf = 0; mf < 4; mf++)
#pragma unroll
            for (int nf = 0; nf < 4; nf++)
                MMA16816(acc[mf][nf], f1.ar[mf], f1.b0r[nf], f1.b1r[nf]);
        // ks=2: load (t,3) over MMA(t,2)
        load_frags(f1, smem, st, 3, wm, wn, lane);
#pragma unroll
        for (int mf = 0; mf < 4; mf++)
#pragma unroll
            for (int nf = 0; nf < 4; nf++)
                MMA16816(acc[mf][nf], f0.ar[mf], f0.b0r[nf], f0.b1r[nf]);
        // ks=3: load (t+1,0) (stage t+1 already readable) over MMA(t,3)
        if (t + 1 < KTILES)
            load_frags(f0, smem, sn, 0, wm, wn, lane);
#pragma unroll
        for (int mf = 0; mf < 4; mf++)
#pragma unroll
            for (int nf = 0; nf < 4; nf++)
                MMA16816(acc[mf][nf], f1.ar[mf], f1.b0r[nf], f1.b1r[nf]);
    }

#pragma unroll
    for (int mf = 0; mf < 4; mf++) {
#pragma unroll
        for (int nf = 0; nf < 4; nf++) {
            int r0 = mtile * 128 + wm * 64 + mf * 16 + (lane >> 2);
            int c0 = ntile * 128 + wn * 32 + nf * 8 + (lane & 3) * 2;
            float b0 = __ldg(&bias[c0]), b1 = __ldg(&bias[c0 + 1]);
            float v00 = acc[mf][nf][0] + b0, v01 = acc[mf][nf][1] + b1;
            float v10 = acc[mf][nf][2] + b0, v11 = acc[mf][nf][3] + b1;
            if (mode == 0) {
                __half2* o0 = (__half2*)((__half*)outv + (size_t)r0 * Nd + c0);
                __half2* o1 = (__half2*)((__half*)outv + (size_t)(r0 + 8) * Nd + c0);
                *o0 = __floats2half2_rn(selu_f(v00), selu_f(v01));
                *o1 = __floats2half2_rn(selu_f(v10), selu_f(v11));
            } else {
                float bc0 = __ldg(&bc[c0]), bc1 = __ldg(&bc[c0 + 1]);
                float fl0 = __ldg(&flag[c0]), fl1 = __ldg(&flag[c0 + 1]);
                float* o0 = (float*)outv + (size_t)r0 * Nd + c0;
                float* o1 = (float*)outv + (size_t)(r0 + 8) * Nd + c0;
                o0[0] = bc0 + v00 * fl0; o0[1] = bc1 + v01 * fl1;
                o1[0] = bc0 + v10 * fl0; o1[1] = bc1 + v11 * fl1;
            }
        }
    }
}

// ---------------- host ----------------
extern "C" void kernel_launch(void* const* d_in, const int* in_sizes, int n_in,
                              void* d_out, int out_size) {
    const float* x    = (const float*)d_in[0];
    const float* vals = (const float*)d_in[1];
    const float* bc   = (const float*)d_in[2];
    const float* flag = (const float*)d_in[3];
    const float* W1   = (const float*)d_in[4];
    const float* b1   = (const float*)d_in[5];
    const float* W2   = (const float*)d_in[6];
    const float* b2   = (const float*)d_in[7];
    const float* W3   = (const float*)d_in[8];
    const float* b3   = (const float*)d_in[9];
    const int*   rows = (const int*)d_in[10];
    const int*   cols = (const int*)d_in[11];

    void *pa0, *ph1, *ph2;
    cudaGetSymbolAddress(&pa0, g_a0h);
    cudaGetSymbolAddress(&ph1, g_h1h);
    cudaGetSymbolAddress(&ph2, g_h2h);

    cudaFuncSetAttribute(gemm_f16_kernel, cudaFuncAttributeMaxDynamicSharedMemorySize, GEMM_SMEM);

    fused_prep_kernel<<<2049, 256>>>(x);                                  // 0
    build_kernel<<<256, 256>>>(rows, cols, vals);                         // 1
    spmv_kernel<<<Nd / 8, 256>>>(bc, flag);                               // 2
    gemm_f16_kernel<<<128, 256, GEMM_SMEM>>>((__half*)pa0, W1, b1, bc, flag, ph1, 0);   // 3 <- ncu
    gemm_f16_kernel<<<128, 256, GEMM_SMEM>>>((__half*)ph1, W2, b2, bc, flag, ph2, 0);   // 4
    gemm_f16_kernel<<<128, 256, GEMM_SMEM>>>((__half*)ph2, W3, b3, bc, flag, d_out, 1); // 5
}

// round 13
// speedup vs baseline: 1.3883x; 1.0006x over previous
#include <cuda_runtime.h>
#include <cuda_fp16.h>
#include <cstdint>
#include <math.h>

static constexpr int Nd   = 8192;
static constexpr int Bd   = 256;
static constexpr int NNZc = 16 * Nd;
static constexpr int SLOTS = 64;          // padded CSR row capacity (max ~38 expected)

// ---------------- device scratch (no allocation) ----------------
__device__ __align__(1024) __half g_xth[Nd * Bd];       // x^T [N,B] fp16
__device__ __align__(1024) __half g_a0h[Bd * Nd];       // activations fp16 [B,N]
__device__ __align__(1024) __half g_h1h[Bd * Nd];
__device__ __align__(1024) __half g_h2h[Bd * Nd];
__device__ int   g_cnt[Nd];
__device__ __align__(1024) int2 g_cv[Nd * SLOTS];       // padded {col, val-bits}

// ---------------- helpers ----------------
__device__ __forceinline__ uint32_t smem_to_u32(const void* p) {
    uint32_t a;
    asm("{ .reg .u64 t; cvta.to.shared.u64 t, %1; cvt.u32.u64 %0, t; }" : "=r"(a) : "l"(p));
    return a;
}

__device__ __forceinline__ float selu_f(float x) {
    const float kS = 1.0507009873554805f;
    const float kA = 1.6732632423543772f;
    return x > 0.f ? kS * x : kS * kA * expm1f(x);
}

// A tile: 128 rows x 64 halves = 128B rows, SW128 (canonical, conflict-free for ldsm)
__device__ __forceinline__ uint32_t swzA64(uint32_t r, uint32_t c) {
    uint32_t byte = r * 128u + c * 2u;
    return byte ^ ((byte >> 3) & 0x70u);
}
// B tile: 128 rows x 64 fp32 = 256B rows.
// XOR row bits (r&7) into byte-bits [7:5] (32B granule): involution, 16B-chunk-preserving,
// and the 8-row x 4-lane lds.64 fragment pattern becomes bank-conflict-free per wavefront.
__device__ __forceinline__ uint32_t swzB64(uint32_t r, uint32_t cw) {
    uint32_t byte = r * 256u + cw * 4u;
    return byte ^ ((byte >> 3) & 0xE0u);
}

#define CP_ASYNC16(dst, src) \
    asm volatile("cp.async.cg.shared.global [%0], [%1], 16;" :: "r"(dst), "l"(src) : "memory")
#define CP_COMMIT() asm volatile("cp.async.commit_group;" ::: "memory")
#define CP_WAIT1()  asm volatile("cp.async.wait_group 1;" ::: "memory")

#define LDMATRIX_X4(r0, r1, r2, r3, addr) \
    asm volatile("ldmatrix.sync.aligned.m8n8.x4.shared.b16 {%0,%1,%2,%3}, [%4];" \
        : "=r"(r0), "=r"(r1), "=r"(r2), "=r"(r3) : "r"(addr))

#define MMA16816(d, a, b0, b1) \
    asm volatile("mma.sync.aligned.m16n8k16.row.col.f32.f16.f16.f32 " \
        "{%0,%1,%2,%3}, {%4,%5,%6,%7}, {%8,%9}, {%0,%1,%2,%3};" \
        : "+f"((d)[0]), "+f"((d)[1]), "+f"((d)[2]), "+f"((d)[3]) \
        : "r"((a)[0]), "r"((a)[1]), "r"((a)[2]), "r"((a)[3]), "r"(b0), "r"(b1))

// ---------------- sparse pipeline (3 launches) ----------------
__global__ void __launch_bounds__(256, 2) fused_prep_kernel(const float* __restrict__ x) {
    if (blockIdx.x < 2048) {
        __shared__ float t[32][33];
        int nb = (blockIdx.x & 255) * 32, bb = (blockIdx.x >> 8) * 32;
        int tx = threadIdx.x & 31, ty = threadIdx.x >> 5;
#pragma unroll
        for (int i = 0; i < 32; i += 8)
            t[ty + i][tx] = x[(size_t)(bb + ty + i) * Nd + nb + tx];
        __syncthreads();
#pragma unroll
        for (int i = 0; i < 32; i += 8)
            g_xth[(size_t)(nb + ty + i) * Bd + bb + tx] = __float2half_rn(t[tx][ty + i]);
    } else {
#pragma unroll
        for (int i = 0; i < Nd / 256; i++) g_cnt[threadIdx.x + i * 256] = 0;
    }
}

__global__ void build_kernel(const int* __restrict__ rows, const int* __restrict__ cols,
                             const float* __restrict__ vals) {
    for (int i = blockIdx.x * blockDim.x + threadIdx.x; i < NNZc; i += gridDim.x * blockDim.x) {
        int r = rows[i];
        int p = atomicAdd(&g_cnt[r], 1);
        g_cv[r * SLOTS + p] = make_int2(cols[i], __float_as_int(vals[i]));
    }
}

__global__ void spmv_kernel(const float* __restrict__ bc, const float* __restrict__ flag) {
    int row = blockIdx.x * 8 + (threadIdx.x >> 5);
    int lane = threadIdx.x & 31;
    int n = g_cnt[row];
    const int2* cv = g_cv + row * SLOTS;
    const __half* xbh = g_xth + lane * 8;
    float a0 = 0.f, a1 = 0.f, a2 = 0.f, a3 = 0.f, a4 = 0.f, a5 = 0.f, a6 = 0.f, a7 = 0.f;
    if (n > 0) {
        int2 c = cv[0];
        uint4 raw = *(const uint4*)(xbh + (size_t)c.x * Bd);
        for (int j = 0; j < n; j++) {
            float v = __int_as_float(c.y);
            int2 cn = c; uint4 rn = raw;
            if (j + 1 < n) {                         // prefetch next (cv, x-row)
                cn = cv[j + 1];
                rn = *(const uint4*)(xbh + (size_t)cn.x * Bd);
            }
            __half2* h = (__half2*)&raw;
            float2 p0 = __half22float2(h[0]);
            float2 p1 = __half22float2(h[1]);
            float2 p2 = __half22float2(h[2]);
            float2 p3 = __half22float2(h[3]);
            a0 += v * p0.x; a1 += v * p0.y; a2 += v * p1.x; a3 += v * p1.y;
            a4 += v * p2.x; a5 += v * p2.y; a6 += v * p3.x; a7 += v * p3.y;
            c = cn; raw = rn;
        }
    }
    float bcv = bc[row], fl = flag[row];
    float r[8] = {a0, a1, a2, a3, a4, a5, a6, a7};
#pragma unroll
    for (int i = 0; i < 8; i++)
        g_a0h[(size_t)(lane * 8 + i) * Nd + row] = __float2half_rn(bcv + r[i] * fl);
}

// ---------------- fp16 mma.sync GEMM, fp32 W converted in-register ----------------
static constexpr int NSTAGE      = 4;
static constexpr int A_BYTES     = 16384;   // 128x64 halves
static constexpr int B_BYTES     = 32768;   // 128x64 fp32
static constexpr int STAGE_BYTES = A_BYTES + B_BYTES;           // 48 KB
static constexpr int GEMM_SMEM   = NSTAGE * STAGE_BYTES;        // 192 KB
static constexpr int KTILES      = Nd / 64; // 128

__device__ __forceinline__ void issue_stage(uint32_t sbase, int buf,
                                            const __half* At, const float* Wt,
                                            int k0, int tid) {
    uint32_t st = sbase + buf * STAGE_BYTES;
    // A: 1024 x 16B chunks (128B/row = 8 chunks)
#pragma unroll
    for (int i = 0; i < 4; i++) {
        int id = tid + i * 256;
        int r = id >> 3, ch = id & 7;
        const __half* src = At + (size_t)r * Nd + k0 + ch * 8;
        CP_ASYNC16(st + swzA64(r, ch * 8), src);
    }
    // B: 2048 x 16B chunks (256B/row = 16 chunks)
#pragma unroll
    for (int i = 0; i < 8; i++) {
        int id = tid + i * 256;
        int r = id >> 4, ch = id & 15;
        const float* src = Wt + (size_t)r * Nd + k0 + ch * 4;
        CP_ASYNC16(st + A_BYTES + swzB64(r, ch * 4), src);
    }
}

struct Frags {
    uint32_t ar[4][4];
    uint32_t b0r[4], b1r[4];
};

__device__ __forceinline__ void load_frags(Frags& f, const char* smem,
                                           int stage, int ks, int wm, int wn, int lane) {
    uint32_t aOff = stage * STAGE_BYTES;
    uint32_t bOff = aOff + A_BYTES;
    uint32_t sb0 = smem_to_u32(smem);
    uint32_t acol = ks * 16 + (lane >> 4) * 8;
#pragma unroll
    for (int mf = 0; mf < 4; mf++) {
        uint32_t row = wm * 64 + mf * 16 + (lane & 15);
        LDMATRIX_X4(f.ar[mf][0], f.ar[mf][1], f.ar[mf][2], f.ar[mf][3],
                    sb0 + aOff + swzA64(row, acol));
    }
    uint32_t nrow = wn * 32 + (lane >> 2);
    uint32_t clo = ks * 16 + (lane & 3) * 2;
#pragma unroll
    for (int nf = 0; nf < 4; nf++) {
        uint32_t r = nrow + nf * 8;
        float2 lo = *(const float2*)(smem + bOff + swzB64(r, clo));
        float2 hi = *(const float2*)(smem + bOff + swzB64(r, clo + 8));
        __half2 h0 = __floats2half2_rn(lo.x, lo.y);
        __half2 h1 = __floats2half2_rn(hi.x, hi.y);
        f.b0r[nf] = *(uint32_t*)&h0;
        f.b1r[nf] = *(uint32_t*)&h1;
    }
}

__global__ void __launch_bounds__(256, 1)
gemm_f16_kernel(const __half* __restrict__ Ag, const float* __restrict__ Wg,
                const float* __restrict__ bias,
                const float* __restrict__ bc, const float* __restrict__ flag,
                void* __restrict__ outv, int mode)   // 0=selu->half, 1=addcmul->float
{
    extern __shared__ char smem[];
    uint32_t sb = smem_to_u32(smem);
    int tid = threadIdx.x, lane = tid & 31, w = tid >> 5;
    int wm = w & 1, wn = w >> 1;
    int mtile = blockIdx.x & 1, ntile = blockIdx.x >> 1;

    const __half* At = Ag + (size_t)(mtile * 128) * Nd;
    const float*  Wt = Wg + (size_t)(ntile * 128) * Nd;

    float acc[4][4][4];
#pragma unroll
    for (int a = 0; a < 4; a++)
#pragma unroll
        for (int b = 0; b < 4; b++)
#pragma unroll
            for (int c = 0; c < 4; c++) acc[a][b][c] = 0.f;

#pragma unroll
    for (int s = 0; s < NSTAGE - 1; s++) {          // stages 0,1,2
        issue_stage(sb, s, At, Wt, s * 64, tid);
        CP_COMMIT();
    }
    // stages 0 AND 1 complete (committed=3, wait_group 1), then preload f0(0,0)
    CP_WAIT1();
    __syncthreads();

    Frags f0, f1;
    load_frags(f0, smem, 0, 0, wm, wn, lane);

#pragma unroll 1
    for (int t = 0; t < KTILES; t++) {
        // committed = 3 + t; wait 1 -> groups 0..t+1 complete -> stages t, t+1 ready
        CP_WAIT1();
        __syncthreads();     // cross-thread visibility of stages t, t+1;
                             // all reads of stage t-1 (overwrite target) are done
        if (t + 3 < KTILES)
            issue_stage(sb, (t + 3) % NSTAGE, At, Wt, (t + 3) * 64, tid);
        CP_COMMIT();         // unconditional: exact group accounting

        int st = t % NSTAGE;
        int sn = (t + 1) % NSTAGE;

        // ks=0: load (t,1) over MMA(t,0)
        load_frags(f1, smem, st, 1, wm, wn, lane);
#pragma unroll
        for (int mf = 0; mf < 4; mf++)
#pragma unroll
            for (int nf = 0; nf < 4; nf++)
                MMA16816(acc[mf][nf], f0.ar[mf], f0.b0r[nf], f0.b1r[nf]);
        // ks=1: load (t,2) over MMA(t,1)
        load_frags(f0, smem, st, 2, wm, wn, lane);
#pragma unroll
        for (int mf = 0; mf < 4; mf++)
#pragma unroll
            for (int nf = 0; nf < 4; nf++)
                MMA16816(acc[mf][nf], f1.ar[mf], f1.b0r[nf], f1.b1r[nf]);
        // ks=2: load (t,3) over MMA(t,2)
        load_frags(f1, smem, st, 3, wm, wn, lane);
#pragma unroll
        for (int mf = 0; mf < 4; mf++)
#pragma unroll
            for (int nf = 0; nf < 4; nf++)
                MMA16816(acc[mf][nf], f0.ar[mf], f0.b0r[nf], f0.b1r[nf]);
        // ks=3: load (t+1,0) (stage t+1 already readable) over MMA(t,3)
        if (t + 1 < KTILES)
            load_frags(f0, smem, sn, 0, wm, wn, lane);
#pragma unroll
        for (int mf = 0; mf < 4; mf++)
#pragma unroll
            for (int nf = 0; nf < 4; nf++)
                MMA16816(acc[mf][nf], f1.ar[mf], f1.b0r[nf], f1.b1r[nf]);
    }

#pragma unroll
    for (int mf = 0; mf < 4; mf++) {
#pragma unroll
        for (int nf = 0; nf < 4; nf++) {
            int r0 = mtile * 128 + wm * 64 + mf * 16 + (lane >> 2);
            int c0 = ntile * 128 + wn * 32 + nf * 8 + (lane & 3) * 2;
            float b0 = __ldg(&bias[c0]), b1 = __ldg(&bias[c0 + 1]);
            float v00 = acc[mf][nf][0] + b0, v01 = acc[mf][nf][1] + b1;
            float v10 = acc[mf][nf][2] + b0, v11 = acc[mf][nf][3] + b1;
            if (mode == 0) {
                __half2* o0 = (__half2*)((__half*)outv + (size_t)r0 * Nd + c0);
                __half2* o1 = (__half2*)((__half*)outv + (size_t)(r0 + 8) * Nd + c0);
                *o0 = __floats2half2_rn(selu_f(v00), selu_f(v01));
                *o1 = __floats2half2_rn(selu_f(v10), selu_f(v11));
            } else {
                float bc0 = __ldg(&bc[c0]), bc1 = __ldg(&bc[c0 + 1]);
                float fl0 = __ldg(&flag[c0]), fl1 = __ldg(&flag[c0 + 1]);
                float* o0 = (float*)outv + (size_t)r0 * Nd + c0;
                float* o1 = (float*)outv + (size_t)(r0 + 8) * Nd + c0;
                o0[0] = bc0 + v00 * fl0; o0[1] = bc1 + v01 * fl1;
                o1[0] = bc0 + v10 * fl0; o1[1] = bc1 + v11 * fl1;
            }
        }
    }
}

// ---------------- host ----------------
extern "C" void kernel_launch(void* const* d_in, const int* in_sizes, int n_in,
                              void* d_out, int out_size) {
    const float* x    = (const float*)d_in[0];
    const float* vals = (const float*)d_in[1];
    const float* bc   = (const float*)d_in[2];
    const float* flag = (const float*)d_in[3];
    const float* W1   = (const float*)d_in[4];
    const float* b1   = (const float*)d_in[5];
    const float* W2   = (const float*)d_in[6];
    const float* b2   = (const float*)d_in[7];
    const float* W3   = (const float*)d_in[8];
    const float* b3   = (const float*)d_in[9];
    const int*   rows = (const int*)d_in[10];
    const int*   cols = (const int*)d_in[11];

    void *pa0, *ph1, *ph2;
    cudaGetSymbolAddress(&pa0, g_a0h);
    cudaGetSymbolAddress(&ph1, g_h1h);
    cudaGetSymbolAddress(&ph2, g_h2h);

    cudaFuncSetAttribute(gemm_f16_kernel, cudaFuncAttributeMaxDynamicSharedMemorySize, GEMM_SMEM);

    fused_prep_kernel<<<2049, 256>>>(x);                                  // 0
    build_kernel<<<256, 256>>>(rows, cols, vals);                         // 1
    spmv_kernel<<<Nd / 8, 256>>>(bc, flag);                               // 2
    gemm_f16_kernel<<<128, 256, GEMM_SMEM>>>((__half*)pa0, W1, b1, bc, flag, ph1, 0);   // 3 <- ncu
    gemm_f16_kernel<<<128, 256, GEMM_SMEM>>>((__half*)ph1, W2, b2, bc, flag, ph2, 0);   // 4
    gemm_f16_kernel<<<128, 256, GEMM_SMEM>>>((__half*)ph2, W3, b3, bc, flag, d_out, 1); // 5
}